// round 2
// baseline (speedup 1.0000x reference)
#include <cuda_runtime.h>
#include <cstdint>
#include <cstddef>

#define N_NODES 100000
#define R_REL   8
#define HF      128

// 8 * 100000 * 128 floats = 409.6 MB scratch for H[r][node][hto]
__device__ float g_H[(size_t)R_REL * N_NODES * HF];

// ---------------------------------------------------------------------------
// helpers
// ---------------------------------------------------------------------------
__device__ __forceinline__ uint32_t f32_to_tf32(float f) {
    uint32_t o;
    asm("cvt.rna.tf32.f32 %0, %1;" : "=r"(o) : "f"(f));
    return o;
}

// ---------------------------------------------------------------------------
// zero out (d_out is poisoned by harness)
// ---------------------------------------------------------------------------
__global__ void zero_kernel(float4* out, int n4) {
    int i = blockIdx.x * blockDim.x + threadIdx.x;
    if (i < n4) out[i] = make_float4(0.f, 0.f, 0.f, 0.f);
}

// ---------------------------------------------------------------------------
// GEMM: H[r] = nodes @ W[r]^T   (tf32 mma.sync, per-block m-tile of 128 rows,
// loops all 8 relations so nodes are read from DRAM exactly once)
// ---------------------------------------------------------------------------
#define LDA 132
#define LDB 132
#define GEMM_SMEM (2 * 128 * 132 * 4)

__global__ __launch_bounds__(256, 1) void rgcn_gemm(
    const float* __restrict__ nodes, const float* __restrict__ weights)
{
    extern __shared__ uint32_t smem[];
    uint32_t* As = smem;             // [128][LDA]  tf32 bits of node tile (row m, col k)
    uint32_t* Bs = smem + 128 * LDA; // [128][LDB]  tf32 bits, Bs[n][k] = W[r][n][k]

    const int tid  = threadIdx.x;
    const int warp = tid >> 5;
    const int lane = tid & 31;
    const int g    = lane >> 2;   // groupID
    const int tg   = lane & 3;    // thread-in-group
    const int m0   = blockIdx.x * 128;
    const int nbase = warp * 16;  // each warp owns 16 output columns

    // ---- load A tile (zero-pad rows >= N_NODES), convert to tf32 ----
    {
        const float4* src = (const float4*)nodes;
        #pragma unroll
        for (int i = tid; i < 128 * 32; i += 256) {
            int row = i >> 5, c4 = i & 31;
            float4 v = make_float4(0.f, 0.f, 0.f, 0.f);
            if (m0 + row < N_NODES) v = src[(size_t)(m0 + row) * 32 + c4];
            uint32_t* d = &As[row * LDA + c4 * 4];
            d[0] = f32_to_tf32(v.x); d[1] = f32_to_tf32(v.y);
            d[2] = f32_to_tf32(v.z); d[3] = f32_to_tf32(v.w);
        }
    }

    for (int r = 0; r < R_REL; r++) {
        __syncthreads();   // prev iter's B-reg loads done (and A fill on first iter)
        // ---- stage W[r] into smem: Bs[n][k] ----
        {
            const float4* src = (const float4*)(weights + (size_t)r * HF * HF);
            #pragma unroll
            for (int i = tid; i < 128 * 32; i += 256) {
                int n = i >> 5, k4 = i & 31;
                float4 v = src[n * 32 + k4];
                uint32_t* d = &Bs[n * LDB + k4 * 4];
                d[0] = f32_to_tf32(v.x); d[1] = f32_to_tf32(v.y);
                d[2] = f32_to_tf32(v.z); d[3] = f32_to_tf32(v.w);
            }
        }
        __syncthreads();

        // ---- B fragments for this warp's 16 columns, all K, held in regs ----
        uint32_t breg[16][2][2];
        #pragma unroll
        for (int kk = 0; kk < 16; kk++) {
            #pragma unroll
            for (int nt = 0; nt < 2; nt++) {
                int n = nbase + nt * 8 + g;
                int k = kk * 8 + tg;
                breg[kk][nt][0] = Bs[n * LDB + k];
                breg[kk][nt][1] = Bs[n * LDB + k + 4];
            }
        }

        float* Hr = g_H + (size_t)r * N_NODES * HF;
        #pragma unroll 1
        for (int msub = 0; msub < 8; msub++) {
            float acc[2][4] = {};
            const int mrow = msub * 16;
            #pragma unroll
            for (int kk = 0; kk < 16; kk++) {
                uint32_t a0 = As[(mrow + g)     * LDA + kk * 8 + tg];
                uint32_t a1 = As[(mrow + g + 8) * LDA + kk * 8 + tg];
                uint32_t a2 = As[(mrow + g)     * LDA + kk * 8 + tg + 4];
                uint32_t a3 = As[(mrow + g + 8) * LDA + kk * 8 + tg + 4];
                #pragma unroll
                for (int nt = 0; nt < 2; nt++) {
                    asm volatile(
                        "mma.sync.aligned.m16n8k8.row.col.f32.tf32.tf32.f32 "
                        "{%0,%1,%2,%3}, {%4,%5,%6,%7}, {%8,%9}, {%0,%1,%2,%3};"
                        : "+f"(acc[nt][0]), "+f"(acc[nt][1]),
                          "+f"(acc[nt][2]), "+f"(acc[nt][3])
                        : "r"(a0), "r"(a1), "r"(a2), "r"(a3),
                          "r"(breg[kk][nt][0]), "r"(breg[kk][nt][1]));
                }
            }
            const int row0 = m0 + mrow + g;
            const int row1 = row0 + 8;
            #pragma unroll
            for (int nt = 0; nt < 2; nt++) {
                int col = nbase + nt * 8 + 2 * tg;
                if (row0 < N_NODES)
                    *(float2*)&Hr[(size_t)row0 * HF + col] = make_float2(acc[nt][0], acc[nt][1]);
                if (row1 < N_NODES)
                    *(float2*)&Hr[(size_t)row1 * HF + col] = make_float2(acc[nt][2], acc[nt][3]);
            }
        }
    }
}

// ---------------------------------------------------------------------------
// Edge scatter: one warp per edge; lane l handles float4 chunk l.
// out[row % N] += value * H[row / N][col]
// NOTE: indices are int32 (JAX x64 is disabled; the .astype(int64) is a no-op
// downcast to int32 in the dataset).
// ---------------------------------------------------------------------------
__global__ __launch_bounds__(256) void rgcn_scatter(
    const int*   __restrict__ rows,
    const int*   __restrict__ cols,
    const float* __restrict__ vals,
    float*       __restrict__ out,
    int nnz)
{
    int e = (int)((blockIdx.x * (unsigned)blockDim.x + threadIdx.x) >> 5);
    int lane = threadIdx.x & 31;
    if (e >= nnz) return;

    int row = rows[e];
    int c   = cols[e];
    float v = vals[e];
    int r = row / N_NODES;
    int n = row - r * N_NODES;

    const float4* src = (const float4*)(g_H + ((size_t)r * N_NODES + c) * HF);
    float4 h = src[lane];

    float* dst = out + (size_t)n * HF + lane * 4;
    asm volatile("red.global.add.v4.f32 [%0], {%1,%2,%3,%4};"
                 :: "l"(dst), "f"(v * h.x), "f"(v * h.y),
                    "f"(v * h.z), "f"(v * h.w)
                 : "memory");
}

// ---------------------------------------------------------------------------
// ReLU in place
// ---------------------------------------------------------------------------
__global__ void relu_kernel(float4* out, int n4) {
    int i = blockIdx.x * blockDim.x + threadIdx.x;
    if (i < n4) {
        float4 v = out[i];
        v.x = fmaxf(v.x, 0.f); v.y = fmaxf(v.y, 0.f);
        v.z = fmaxf(v.z, 0.f); v.w = fmaxf(v.w, 0.f);
        out[i] = v;
    }
}

// ---------------------------------------------------------------------------
extern "C" void kernel_launch(void* const* d_in, const int* in_sizes, int n_in,
                              void* d_out, int out_size) {
    const float* nodes   = (const float*)d_in[0];
    const int*   indices = (const int*)d_in[1];     // int32! (jax x64 disabled)
    const float* vals    = (const float*)d_in[2];
    const float* weights = (const float*)d_in[3];
    float* out = (float*)d_out;

    const int nnz  = in_sizes[2];          // 1,600,000
    const int n4   = N_NODES * HF / 4;     // 3,200,000 float4s in out

    zero_kernel<<<(n4 + 255) / 256, 256>>>((float4*)out, n4);

    cudaFuncSetAttribute(rgcn_gemm, cudaFuncAttributeMaxDynamicSharedMemorySize,
                         GEMM_SMEM);
    rgcn_gemm<<<(N_NODES + 127) / 128, 256, GEMM_SMEM>>>(nodes, weights);

    rgcn_scatter<<<(nnz + 7) / 8, 256>>>(indices, indices + nnz, vals, out, nnz);

    relu_kernel<<<(n4 + 255) / 256, 256>>>((float4*)out, n4);
}